// round 12
// baseline (speedup 1.0000x reference)
#include <cuda_runtime.h>
#include <cuda_bf16.h>
#include <math.h>

// Problem constants
#define B    256
#define T    2048
#define D    64
#define N    128
#define LEAK 0.5f

// ---------------------------------------------------------------------------
// XLA ElementalIrEmitter::EmitTanh replica — VERIFIED BITWISE vs reference:
//   clamp 7.99881172180175781, |x|<0.0004 passthrough, contracted (FMA)
//   Horner for numerator/denominator, IEEE divide.
// ---------------------------------------------------------------------------
__device__ __forceinline__ float tanh_xla(float x) {
    const float kClamp = 7.99881172180175781f;
    const float kTiny  = 0.0004f;
    float cx = fminf(fmaxf(x, -kClamp), kClamp);
    float x2 = __fmul_rn(cx, cx);
    float p = -2.76076847742355e-16f;
    p = __fmaf_rn(x2, p, 2.00018790482477e-13f);
    p = __fmaf_rn(x2, p, -8.60467152213735e-11f);
    p = __fmaf_rn(x2, p, 5.12229709037114e-08f);
    p = __fmaf_rn(x2, p, 1.48572235717979e-05f);
    p = __fmaf_rn(x2, p, 6.37261928875436e-04f);
    p = __fmaf_rn(x2, p, 4.89352455891786e-03f);
    p = __fmul_rn(cx, p);
    float q = 1.19825839466702e-06f;
    q = __fmaf_rn(x2, q, 1.18534705686654e-04f);
    q = __fmaf_rn(x2, q, 2.26843463243900e-03f);
    q = __fmaf_rn(x2, q, 4.89352518554385e-03f);
    float r = __fdiv_rn(p, q);
    return (fabsf(x) < kTiny) ? x : r;
}

// ---------------------------------------------------------------------------
// Fully fused ESN kernel. Grid = 128 CTAs (one per batch pair), 256 threads:
// par = tid>>7 (which batch of the pair), n = tid&127 (output column).
//
// Per step t (per thread, all bitwise-identical to the verified semantics):
//   - state chain: acc = 128 ascending-k dependent FMAs over st[(t-1)&1]
//     (serial 512 cyc — the critical path)
//   - u-chain for t+1: 64 ascending-d FMAs over x[t+1] (staged in SMEM) and
//     W_in column n (SMEM [d][n], conflict-free) + b_in  — fully independent
//     of the state chain; hides in its issue gaps
//   - stage x[t+2] (lanes n<64, one coalesced LDG -> STS)
//   - epilogue: arg=(u[t]+acc)+b_res; tanh; xv = 0.5*xv + 0.5*tanh
//   - named per-group barrier (ids 1,2); output STG after the barrier
// ---------------------------------------------------------------------------
__global__ __launch_bounds__(256, 1) void esn_fused_kernel(
    const float* __restrict__ x,
    const float* __restrict__ W_in,
    const float* __restrict__ b_in,
    const float* __restrict__ W_res,
    const float* __restrict__ b_res,
    float* __restrict__ X)
{
    __shared__ __align__(16) float st[2][2][N];     // [buf][par][n]
    __shared__ __align__(16) float wsh[D][N];       // W_in, [d][n]
    __shared__ __align__(16) float xb[2][2][D];     // [par][buf][d]

    const int tid = threadIdx.x;
    const int par = tid >> 7;
    const int n   = tid & (N - 1);
    const int b   = 2 * blockIdx.x + par;
    const int barid = par + 1;

    // W_res column in registers (verified layout)
    float w[N];
#pragma unroll
    for (int k = 0; k < N; k++) w[k] = W_res[k * N + n];
    const float brv = b_res[n];
    const float biv = b_in[n];

    // cooperative W_in stage: [d][n]
    for (int idx = tid; idx < D * N; idx += 256) {
        int d = idx >> 7, c = idx & (N - 1);
        wsh[d][c] = W_in[d * N + c];
    }

    const float* xrow = x + (size_t)b * T * D;
    float* xo = X + (size_t)b * T * N + n;

    // stage x[0], x[1]
    if (n < D) {
        xb[par][0][n] = xrow[n];
        xb[par][1][n] = xrow[D + n];
    }
    __syncthreads();

    // ---- prologue: u[0] -> x0 state; u[1] ----
    float xv, un;
    {
        const float4* xq = reinterpret_cast<const float4*>(xb[par][0]);
        float uacc = 0.f;
#pragma unroll
        for (int j = 0; j < D / 4; j++) {
            float4 c = xq[j];
            uacc = __fmaf_rn(c.x, wsh[4 * j][n],     uacc);
            uacc = __fmaf_rn(c.y, wsh[4 * j + 1][n], uacc);
            uacc = __fmaf_rn(c.z, wsh[4 * j + 2][n], uacc);
            uacc = __fmaf_rn(c.w, wsh[4 * j + 3][n], uacc);
        }
        float u0 = __fadd_rn(uacc, biv);
        xv = __fmul_rn(LEAK, tanh_xla(u0));
        st[0][par][n] = xv;
        xo[0] = xv;

        xq = reinterpret_cast<const float4*>(xb[par][1]);
        uacc = 0.f;
#pragma unroll
        for (int j = 0; j < D / 4; j++) {
            float4 c = xq[j];
            uacc = __fmaf_rn(c.x, wsh[4 * j][n],     uacc);
            uacc = __fmaf_rn(c.y, wsh[4 * j + 1][n], uacc);
            uacc = __fmaf_rn(c.z, wsh[4 * j + 2][n], uacc);
            uacc = __fmaf_rn(c.w, wsh[4 * j + 3][n], uacc);
        }
        un = __fadd_rn(uacc, biv);        // u[1]
    }
    // stage x[2] into xb[par][0]
    if (n < D) xb[par][0][n] = xrow[(size_t)2 * D + n];
    asm volatile("bar.sync %0, %1;" :: "r"(barid), "r"(128) : "memory");

    // ---- main loop ----
    for (int t = 1; t < T; t++) {
        const float uthis = un;           // u[t]

        // state chain: depth-4 rotating float4 prefetch, 128 ascending-k FMAs
        const float4* xp4 =
            reinterpret_cast<const float4*>(st[(t - 1) & 1][par]);
        float4 f0 = xp4[0];
        float4 f1 = xp4[1];
        float4 f2 = xp4[2];
        float4 f3 = xp4[3];
        float acc = 0.f;
#pragma unroll
        for (int j = 0; j < 32; j++) {
            float4 c = f0;
            f0 = f1; f1 = f2; f2 = f3;
            if (j < 28) f3 = xp4[j + 4];
            acc = __fmaf_rn(c.x, w[4 * j],     acc);
            acc = __fmaf_rn(c.y, w[4 * j + 1], acc);
            acc = __fmaf_rn(c.z, w[4 * j + 2], acc);
            acc = __fmaf_rn(c.w, w[4 * j + 3], acc);
        }

        // u-chain for t+1 (independent of the state chain; fills issue gaps)
        float unext = 0.f;
        if (t < T - 1) {
            const float4* xq =
                reinterpret_cast<const float4*>(xb[par][(t + 1) & 1]);
            float uacc = 0.f;
#pragma unroll
            for (int j = 0; j < D / 4; j++) {
                float4 c = xq[j];
                uacc = __fmaf_rn(c.x, wsh[4 * j][n],     uacc);
                uacc = __fmaf_rn(c.y, wsh[4 * j + 1][n], uacc);
                uacc = __fmaf_rn(c.z, wsh[4 * j + 2][n], uacc);
                uacc = __fmaf_rn(c.w, wsh[4 * j + 3][n], uacc);
            }
            unext = __fadd_rn(uacc, biv);
        }

        // stage x[t+2]
        if (t < T - 2 && n < D)
            xb[par][t & 1][n] = xrow[(size_t)(t + 2) * D + n];

        // epilogue: arg=(u+dot)+b_res; x = 0.5 x + 0.5 tanh(arg)
        float arg = __fadd_rn(__fadd_rn(uthis, acc), brv);
        float th  = tanh_xla(arg);
        xv = __fadd_rn(__fmul_rn(1.0f - LEAK, xv), __fmul_rn(LEAK, th));

        st[t & 1][par][n] = xv;
        un = unext;
        asm volatile("bar.sync %0, %1;" :: "r"(barid), "r"(128) : "memory");
        xo[(size_t)t * N] = xv;           // off the serial path
    }
}

// ---------------------------------------------------------------------------
extern "C" void kernel_launch(void* const* d_in, const int* in_sizes, int n_in,
                              void* d_out, int out_size)
{
    const float* x     = (const float*)d_in[0];
    const float* W_in  = (const float*)d_in[1];
    const float* b_in  = (const float*)d_in[2];
    const float* W_res = (const float*)d_in[3];
    const float* b_res = (const float*)d_in[4];
    float* X = (float*)d_out;

    esn_fused_kernel<<<B / 2, 256>>>(x, W_in, b_in, W_res, b_res, X);
}

// round 13
// speedup vs baseline: 1.2698x; 1.2698x over previous
#include <cuda_runtime.h>
#include <cuda_bf16.h>
#include <math.h>

// Problem constants
#define B    256
#define T    2048
#define D    64
#define N    128
#define LEAK 0.5f

// ---------------------------------------------------------------------------
// XLA ElementalIrEmitter::EmitTanh replica — VERIFIED BITWISE vs reference:
//   clamp 7.99881172180175781, |x|<0.0004 passthrough, contracted (FMA)
//   Horner for numerator/denominator, IEEE divide.
// ---------------------------------------------------------------------------
__device__ __forceinline__ float tanh_xla(float x) {
    const float kClamp = 7.99881172180175781f;
    const float kTiny  = 0.0004f;
    float cx = fminf(fmaxf(x, -kClamp), kClamp);
    float x2 = __fmul_rn(cx, cx);
    float p = -2.76076847742355e-16f;
    p = __fmaf_rn(x2, p, 2.00018790482477e-13f);
    p = __fmaf_rn(x2, p, -8.60467152213735e-11f);
    p = __fmaf_rn(x2, p, 5.12229709037114e-08f);
    p = __fmaf_rn(x2, p, 1.48572235717979e-05f);
    p = __fmaf_rn(x2, p, 6.37261928875436e-04f);
    p = __fmaf_rn(x2, p, 4.89352455891786e-03f);
    p = __fmul_rn(cx, p);
    float q = 1.19825839466702e-06f;
    q = __fmaf_rn(x2, q, 1.18534705686654e-04f);
    q = __fmaf_rn(x2, q, 2.26843463243900e-03f);
    q = __fmaf_rn(x2, q, 4.89352518554385e-03f);
    float r = __fdiv_rn(p, q);
    return (fabsf(x) < kTiny) ? x : r;
}

// ---------------------------------------------------------------------------
// Fully fused ESN kernel — one batch per CTA, 128 threads (thread = column n).
// __launch_bounds__(128,1) -> up to 255 regs/thread: BOTH weight columns live
// in registers (w[128] = W_res[:,n], win[64] = W_in[:,n]) — no LDS for
// weights, no spills.
//
// Per step t (bitwise-identical to the verified reference semantics):
//   - state chain: 128 ascending-k dependent FMAs over st[(t-1)&1]
//     (serial ~512 cyc — the critical path), depth-4 rotating float4 prefetch
//   - u-chain for t+1: 64 ascending-d FMAs over x[t+1] (SMEM) and win (regs)
//     + b_in — independent of the state chain, fills its issue gaps
//   - stage x[t+2] (threads n<64, one coalesced LDG -> STS, 2 steps ahead)
//   - epilogue: arg=(u[t]+acc)+b_res; tanh; xv = 0.5*xv + 0.5*tanh
//   - __syncthreads (4 warps); output STG after the barrier
// ---------------------------------------------------------------------------
__global__ __launch_bounds__(128, 1) void esn_fused_kernel(
    const float* __restrict__ x,
    const float* __restrict__ W_in,
    const float* __restrict__ b_in,
    const float* __restrict__ W_res,
    const float* __restrict__ b_res,
    float* __restrict__ X)
{
    __shared__ __align__(16) float st[2][N];    // state double buffer
    __shared__ __align__(16) float xb[2][D];    // x rows, 2-step lookahead

    const int n = threadIdx.x;
    const int b = blockIdx.x;

    // both weight columns in registers
    float w[N];
#pragma unroll
    for (int k = 0; k < N; k++) w[k] = W_res[k * N + n];
    float win[D];
#pragma unroll
    for (int d = 0; d < D; d++) win[d] = W_in[d * N + n];
    const float brv = b_res[n];
    const float biv = b_in[n];

    const float* xrow = x + (size_t)b * T * D;
    float* xo = X + (size_t)b * T * N + n;

    // stage x[0], x[1]
    if (n < D) {
        xb[0][n] = xrow[n];
        xb[1][n] = xrow[D + n];
    }
    __syncthreads();

    // ---- prologue: u[0] -> x0 state; u[1] ----
    float xv, un;
    {
        const float4* xq = reinterpret_cast<const float4*>(xb[0]);
        float uacc = 0.f;
#pragma unroll
        for (int j = 0; j < D / 4; j++) {
            float4 c = xq[j];
            uacc = __fmaf_rn(c.x, win[4 * j],     uacc);
            uacc = __fmaf_rn(c.y, win[4 * j + 1], uacc);
            uacc = __fmaf_rn(c.z, win[4 * j + 2], uacc);
            uacc = __fmaf_rn(c.w, win[4 * j + 3], uacc);
        }
        float u0 = __fadd_rn(uacc, biv);
        xv = __fmul_rn(LEAK, tanh_xla(u0));
        st[0][n] = xv;
        xo[0] = xv;

        xq = reinterpret_cast<const float4*>(xb[1]);
        uacc = 0.f;
#pragma unroll
        for (int j = 0; j < D / 4; j++) {
            float4 c = xq[j];
            uacc = __fmaf_rn(c.x, win[4 * j],     uacc);
            uacc = __fmaf_rn(c.y, win[4 * j + 1], uacc);
            uacc = __fmaf_rn(c.z, win[4 * j + 2], uacc);
            uacc = __fmaf_rn(c.w, win[4 * j + 3], uacc);
        }
        un = __fadd_rn(uacc, biv);        // u[1]
    }
    // all xb[0] reads done before overwrite (fixes R12 latent race)
    __syncthreads();
    if (n < D) xb[0][n] = xrow[(size_t)2 * D + n];   // stage x[2]
    __syncthreads();

    // ---- main loop ----
    for (int t = 1; t < T; t++) {
        const float uthis = un;           // u[t]

        // state chain: depth-4 rotating float4 prefetch, 128 ascending-k FMAs
        const float4* xp4 = reinterpret_cast<const float4*>(st[(t - 1) & 1]);
        float4 f0 = xp4[0];
        float4 f1 = xp4[1];
        float4 f2 = xp4[2];
        float4 f3 = xp4[3];
        float acc = 0.f;
#pragma unroll
        for (int j = 0; j < 32; j++) {
            float4 c = f0;
            f0 = f1; f1 = f2; f2 = f3;
            if (j < 28) f3 = xp4[j + 4];
            acc = __fmaf_rn(c.x, w[4 * j],     acc);
            acc = __fmaf_rn(c.y, w[4 * j + 1], acc);
            acc = __fmaf_rn(c.z, w[4 * j + 2], acc);
            acc = __fmaf_rn(c.w, w[4 * j + 3], acc);
        }

        // u-chain for t+1 (register weights; fills state-chain issue gaps)
        float unext = 0.f;
        if (t < T - 1) {
            const float4* xq =
                reinterpret_cast<const float4*>(xb[(t + 1) & 1]);
            float uacc = 0.f;
#pragma unroll
            for (int j = 0; j < D / 4; j++) {
                float4 c = xq[j];
                uacc = __fmaf_rn(c.x, win[4 * j],     uacc);
                uacc = __fmaf_rn(c.y, win[4 * j + 1], uacc);
                uacc = __fmaf_rn(c.z, win[4 * j + 2], uacc);
                uacc = __fmaf_rn(c.w, win[4 * j + 3], uacc);
            }
            unext = __fadd_rn(uacc, biv);
        }

        // stage x[t+2] into the buffer just freed this step
        if (t < T - 2 && n < D)
            xb[t & 1][n] = xrow[(size_t)(t + 2) * D + n];

        // epilogue: arg=(u+dot)+b_res; x = 0.5 x + 0.5 tanh(arg)
        float arg = __fadd_rn(__fadd_rn(uthis, acc), brv);
        float th  = tanh_xla(arg);
        xv = __fadd_rn(__fmul_rn(1.0f - LEAK, xv), __fmul_rn(LEAK, th));

        st[t & 1][n] = xv;
        un = unext;
        __syncthreads();
        xo[(size_t)t * N] = xv;           // off the serial path
    }
}

// ---------------------------------------------------------------------------
extern "C" void kernel_launch(void* const* d_in, const int* in_sizes, int n_in,
                              void* d_out, int out_size)
{
    const float* x     = (const float*)d_in[0];
    const float* W_in  = (const float*)d_in[1];
    const float* b_in  = (const float*)d_in[2];
    const float* W_res = (const float*)d_in[3];
    const float* b_res = (const float*)d_in[4];
    float* X = (float*)d_out;

    esn_fused_kernel<<<B, 128>>>(x, W_in, b_in, W_res, b_res, X);
}